// round 1
// baseline (speedup 1.0000x reference)
#include <cuda_runtime.h>
#include <math.h>

#define EMBED  1024
#define HIDDEN 512
#define NB     4
#define SQ     4096
#define SKV    4096
#define MTOK   (NB * SQ)   // 16384

// ---------------- scratch (static device arrays; no allocations) ----------------
__device__ float g_Q [(size_t)MTOK * HIDDEN];        //  32 MB
__device__ float g_K [(size_t)MTOK * HIDDEN];        //  32 MB
__device__ float g_V [(size_t)MTOK * HIDDEN];        //  32 MB
__device__ float g_S [(size_t)NB * SQ * SKV];        // 268 MB  attention scores/probs
__device__ float g_C [(size_t)MTOK * HIDDEN];        //  32 MB  context
__device__ float g_O1[(size_t)MTOK * EMBED];         //  64 MB  after Wo + bias + residual
__device__ float g_O2[(size_t)MTOK * EMBED];         //  64 MB  after Wfc

// ---------------- tiled SGEMM: C = A @ B (or A @ B^T), 128x128 tile, K-step 8 ----
// A: [M,K] row-major. B: [K,N] row-major (TB=false) or [N,K] row-major (TB=true).
// Optional epilogue: + bias[col] + res[row,col]. Batch via blockIdx.z with strides.
// Requires M,N multiples of 128 and K multiple of 8 (true for all calls here).
template <bool TB>
__global__ __launch_bounds__(256, 2)
void sgemm128(const float* __restrict__ A, const float* __restrict__ Bm,
              float* __restrict__ C,
              int M, int N, int K,
              long long sA, long long sB, long long sC,
              const float* __restrict__ bias,
              const float* __restrict__ res)
{
    A  += (long long)blockIdx.z * sA;
    Bm += (long long)blockIdx.z * sB;
    C  += (long long)blockIdx.z * sC;
    if (res) res += (long long)blockIdx.z * sC;

    __shared__ float As[8][128];
    __shared__ float Bs[8][128];

    const int tid = threadIdx.x;
    const int tx  = tid & 15;       // 0..15 (cols)
    const int ty  = tid >> 4;       // 0..15 (rows)
    const int m0  = blockIdx.y * 128;
    const int n0  = blockIdx.x * 128;

    // load mapping for A (and B when TB): 128 rows x 8 k, float4 per thread
    const int arow = tid >> 1;            // 0..127
    const int acol = (tid & 1) * 4;       // 0 or 4
    // load mapping for B when NN: 8 k-rows x 128 cols
    const int brow = tid >> 5;            // 0..7
    const int bcol = (tid & 31) * 4;      // 0..124

    float acc[8][8];
    for (int i = 0; i < 8; i++)
        for (int j = 0; j < 8; j++) acc[i][j] = 0.0f;

    const float* Aptr = A + (long long)(m0 + arow) * K + acol;
    const float* Bptr = TB ? (Bm + (long long)(n0 + arow) * K + acol)
                           : (Bm + (long long)brow * N + n0 + bcol);

    for (int k0 = 0; k0 < K; k0 += 8) {
        float4 a = *(const float4*)(Aptr + k0);
        As[acol + 0][arow] = a.x;
        As[acol + 1][arow] = a.y;
        As[acol + 2][arow] = a.z;
        As[acol + 3][arow] = a.w;
        if (TB) {
            float4 b = *(const float4*)(Bptr + k0);
            Bs[acol + 0][arow] = b.x;
            Bs[acol + 1][arow] = b.y;
            Bs[acol + 2][arow] = b.z;
            Bs[acol + 3][arow] = b.w;
        } else {
            float4 b = *(const float4*)(Bptr + (long long)k0 * N);
            *(float4*)&Bs[brow][bcol] = b;
        }
        __syncthreads();

        #pragma unroll
        for (int k = 0; k < 8; k++) {
            float4 a0 = *(float4*)&As[k][ty * 4];
            float4 a1 = *(float4*)&As[k][64 + ty * 4];
            float4 b0 = *(float4*)&Bs[k][tx * 4];
            float4 b1 = *(float4*)&Bs[k][64 + tx * 4];
            float ar[8] = {a0.x, a0.y, a0.z, a0.w, a1.x, a1.y, a1.z, a1.w};
            float br[8] = {b0.x, b0.y, b0.z, b0.w, b1.x, b1.y, b1.z, b1.w};
            #pragma unroll
            for (int i = 0; i < 8; i++)
                #pragma unroll
                for (int j = 0; j < 8; j++)
                    acc[i][j] = fmaf(ar[i], br[j], acc[i][j]);
        }
        __syncthreads();
    }

    // epilogue: vectorized float4 stores
    #pragma unroll
    for (int hi = 0; hi < 2; hi++) {
        #pragma unroll
        for (int i = 0; i < 4; i++) {
            const int row = m0 + hi * 64 + ty * 4 + i;
            #pragma unroll
            for (int hj = 0; hj < 2; hj++) {
                const int col = n0 + hj * 64 + tx * 4;
                float4 v;
                v.x = acc[hi * 4 + i][hj * 4 + 0];
                v.y = acc[hi * 4 + i][hj * 4 + 1];
                v.z = acc[hi * 4 + i][hj * 4 + 2];
                v.w = acc[hi * 4 + i][hj * 4 + 3];
                if (bias) {
                    float4 bv = *(const float4*)&bias[col];
                    v.x += bv.x; v.y += bv.y; v.z += bv.z; v.w += bv.w;
                }
                if (res) {
                    float4 rv = *(const float4*)&res[(long long)row * N + col];
                    v.x += rv.x; v.y += rv.y; v.z += rv.z; v.w += rv.w;
                }
                *(float4*)&C[(long long)row * N + col] = v;
            }
        }
    }
}

// ---------------- block reductions ----------------
__device__ __forceinline__ float blockReduceSum(float v, float* sh)
{
    const int t = threadIdx.x;
    #pragma unroll
    for (int o = 16; o; o >>= 1) v += __shfl_xor_sync(0xFFFFFFFFu, v, o);
    if ((t & 31) == 0) sh[t >> 5] = v;
    __syncthreads();
    if (t < 32) {
        float r = (t < 8) ? sh[t] : 0.0f;
        #pragma unroll
        for (int o = 4; o; o >>= 1) r += __shfl_xor_sync(0xFFFFFFFFu, r, o);
        if (t == 0) sh[0] = r;
    }
    __syncthreads();
    float r = sh[0];
    __syncthreads();
    return r;
}

__device__ __forceinline__ float blockReduceMax(float v, float* sh)
{
    const int t = threadIdx.x;
    #pragma unroll
    for (int o = 16; o; o >>= 1) v = fmaxf(v, __shfl_xor_sync(0xFFFFFFFFu, v, o));
    if ((t & 31) == 0) sh[t >> 5] = v;
    __syncthreads();
    if (t < 32) {
        float r = (t < 8) ? sh[t] : -1e30f;
        #pragma unroll
        for (int o = 4; o; o >>= 1) r = fmaxf(r, __shfl_xor_sync(0xFFFFFFFFu, r, o));
        if (t == 0) sh[0] = r;
    }
    __syncthreads();
    float r = sh[0];
    __syncthreads();
    return r;
}

// ---------------- softmax over rows of S (in place), with pre-scale ----------------
__global__ void softmax_kernel(float* __restrict__ S, int ncols, float scale)
{
    float* p = S + (long long)blockIdx.x * ncols;
    const int t = threadIdx.x;
    __shared__ float sh[32];

    float m = -1e30f;
    for (int i = t; i < ncols; i += 256) m = fmaxf(m, p[i]);
    m = blockReduceMax(m, sh);

    float sum = 0.0f;
    for (int i = t; i < ncols; i += 256) {
        float e = __expf((p[i] - m) * scale);
        p[i] = e;
        sum += e;
    }
    sum = blockReduceSum(sum, sh);

    const float rinv = 1.0f / sum;
    for (int i = t; i < ncols; i += 256) p[i] *= rinv;
}

// ---------------- layernorm over last dim (1024), two-pass ----------------
__global__ void layernorm_kernel(const float* __restrict__ X,
                                 const float* __restrict__ gamma,
                                 const float* __restrict__ beta,
                                 float* __restrict__ Y)
{
    const float* x = X + (long long)blockIdx.x * EMBED;
    float*       y = Y + (long long)blockIdx.x * EMBED;
    const int t = threadIdx.x;   // 256 threads, 4 elems each
    __shared__ float sh[32];

    float4 v = *(const float4*)&x[t * 4];
    float s = v.x + v.y + v.z + v.w;
    s = blockReduceSum(s, sh);
    const float mu = s * (1.0f / EMBED);

    float dx = v.x - mu, dy = v.y - mu, dz = v.z - mu, dw = v.w - mu;
    float sq = dx * dx + dy * dy + dz * dz + dw * dw;
    sq = blockReduceSum(sq, sh);
    const float rstd = rsqrtf(sq * (1.0f / EMBED) + 1e-5f);

    float4 g = *(const float4*)&gamma[t * 4];
    float4 b = *(const float4*)&beta[t * 4];
    float4 o;
    o.x = dx * rstd * g.x + b.x;
    o.y = dy * rstd * g.y + b.y;
    o.z = dz * rstd * g.z + b.z;
    o.w = dw * rstd * g.w + b.w;
    *(float4*)&y[t * 4] = o;
}

// ---------------- launch ----------------
extern "C" void kernel_launch(void* const* d_in, const int* in_sizes, int n_in,
                              void* d_out, int out_size)
{
    const float* q_feat = (const float*)d_in[0];
    const float* kv     = (const float*)d_in[1];
    const float* Wq     = (const float*)d_in[2];
    const float* Wk     = (const float*)d_in[3];
    const float* Wv     = (const float*)d_in[4];
    const float* Wo     = (const float*)d_in[5];
    const float* bo     = (const float*)d_in[6];
    const float* Wfc    = (const float*)d_in[7];
    const float* gamma  = (const float*)d_in[8];
    const float* beta   = (const float*)d_in[9];
    float* out = (float*)d_out;

    float *Q, *Kp, *Vp, *S, *C, *O1, *O2;
    cudaGetSymbolAddress((void**)&Q,  g_Q);
    cudaGetSymbolAddress((void**)&Kp, g_K);
    cudaGetSymbolAddress((void**)&Vp, g_V);
    cudaGetSymbolAddress((void**)&S,  g_S);
    cudaGetSymbolAddress((void**)&C,  g_C);
    cudaGetSymbolAddress((void**)&O1, g_O1);
    cudaGetSymbolAddress((void**)&O2, g_O2);

    const dim3 blk(256);
    const float scale = 0.044194173824159216f;  // 1/sqrt(512)

    // Q/K/V projections: [16384,1024] @ [1024,512]
    sgemm128<false><<<dim3(HIDDEN / 128, MTOK / 128, 1), blk>>>(
        q_feat, Wq, Q, MTOK, HIDDEN, EMBED, 0, 0, 0, nullptr, nullptr);
    sgemm128<false><<<dim3(HIDDEN / 128, MTOK / 128, 1), blk>>>(
        kv, Wk, Kp, MTOK, HIDDEN, EMBED, 0, 0, 0, nullptr, nullptr);
    sgemm128<false><<<dim3(HIDDEN / 128, MTOK / 128, 1), blk>>>(
        kv, Wv, Vp, MTOK, HIDDEN, EMBED, 0, 0, 0, nullptr, nullptr);

    // scores = Q @ K^T per batch: [4096,512] @ [4096,512]^T
    sgemm128<true><<<dim3(SKV / 128, SQ / 128, NB), blk>>>(
        Q, Kp, S, SQ, SKV, HIDDEN,
        (long long)SQ * HIDDEN, (long long)SKV * HIDDEN, (long long)SQ * SKV,
        nullptr, nullptr);

    // softmax rows (scale folded in)
    softmax_kernel<<<NB * SQ, 256>>>(S, SKV, scale);

    // ctx = attn @ V per batch: [4096,4096] @ [4096,512]
    sgemm128<false><<<dim3(HIDDEN / 128, SQ / 128, NB), blk>>>(
        S, Vp, C, SQ, HIDDEN, SKV,
        (long long)SQ * SKV, (long long)SKV * HIDDEN, (long long)SQ * HIDDEN,
        nullptr, nullptr);

    // out = ctx @ Wo + bo + q_feat : [16384,512] @ [512,1024]
    sgemm128<false><<<dim3(EMBED / 128, MTOK / 128, 1), blk>>>(
        C, Wo, O1, MTOK, EMBED, HIDDEN, 0, 0, 0, bo, q_feat);

    // fc = out @ Wfc : [16384,1024] @ [1024,1024]
    sgemm128<false><<<dim3(EMBED / 128, MTOK / 128, 1), blk>>>(
        O1, Wfc, O2, MTOK, EMBED, EMBED, 0, 0, 0, nullptr, nullptr);

    // layernorm -> d_out
    layernorm_kernel<<<MTOK, 256>>>(O2, gamma, beta, out);
}

// round 3
// speedup vs baseline: 4.0427x; 4.0427x over previous
#include <cuda_runtime.h>
#include <cuda_bf16.h>
#include <cstdint>
#include <math.h>

#define EMBED  1024
#define HIDDEN 512
#define NB     4
#define SQ     4096
#define SKV    4096
#define MTOK   (NB * SQ)   // 16384

typedef __nv_bfloat16 bf16;
typedef __nv_bfloat162 bf162;

// ---------------- scratch (static device arrays; no allocations) ----------------
__device__ float g_V  [(size_t)MTOK * HIDDEN];          // fp32 V
__device__ float g_S  [(size_t)NB * SQ * SKV];          // fp32 scores
__device__ float g_O2 [(size_t)MTOK * EMBED];           // fp32 pre-LN

__device__ bf16 g_qs  [(size_t)MTOK * 3 * EMBED];       // A-split q_feat
__device__ bf16 g_kvs [(size_t)MTOK * 3 * EMBED];       // A-split kv_feat
__device__ bf16 g_Qs  [(size_t)MTOK * 3 * HIDDEN];      // A-split Q
__device__ bf16 g_Ks  [(size_t)MTOK * 3 * HIDDEN];      // B-split K
__device__ bf16 g_VTs [(size_t)NB * HIDDEN * 3 * SQ];   // B-split V^T per batch
__device__ bf16 g_Ss  [(size_t)MTOK * 3 * SKV];         // A-split probs (per-batch k segs)
__device__ bf16 g_Cs  [(size_t)MTOK * 3 * HIDDEN];      // A-split ctx
__device__ bf16 g_O1s [(size_t)MTOK * 3 * EMBED];       // A-split (ctx@Wo + bo + qf)
__device__ bf16 g_WqTs [(size_t)HIDDEN * 3 * EMBED];    // B-split Wq^T
__device__ bf16 g_WkTs [(size_t)HIDDEN * 3 * EMBED];
__device__ bf16 g_WvTs [(size_t)HIDDEN * 3 * EMBED];
__device__ bf16 g_WoTs [(size_t)EMBED * 3 * HIDDEN];    // B-split Wo^T
__device__ bf16 g_WfcTs[(size_t)EMBED * 3 * EMBED];     // B-split Wfc^T

// ================= helpers =================
__device__ __forceinline__ uint32_t smem_u32(const void* p) {
    return (uint32_t)__cvta_generic_to_shared((void*)p);
}
#define SWZ128(o) ((o) ^ (((o) >> 3) & 0x70))

__device__ __forceinline__ void cpa16(uint32_t s, const void* g) {
    asm volatile("cp.async.cg.shared.global [%0], [%1], 16;" :: "r"(s), "l"(g));
}
__device__ __forceinline__ void cpa_commit() {
    asm volatile("cp.async.commit_group;" ::: "memory");
}
template <int N> __device__ __forceinline__ void cpa_wait() {
    asm volatile("cp.async.wait_group %0;" :: "n"(N) : "memory");
}
__device__ __forceinline__ void ldsm_x4(uint32_t a, uint32_t& r0, uint32_t& r1,
                                        uint32_t& r2, uint32_t& r3) {
    asm volatile("ldmatrix.sync.aligned.m8n8.x4.shared.b16 {%0,%1,%2,%3}, [%4];"
                 : "=r"(r0), "=r"(r1), "=r"(r2), "=r"(r3) : "r"(a));
}
__device__ __forceinline__ void mma16816(float* c, const uint32_t* a, const uint32_t* b) {
    asm volatile("mma.sync.aligned.m16n8k16.row.col.f32.bf16.bf16.f32 "
                 "{%0,%1,%2,%3}, {%4,%5,%6,%7}, {%8,%9}, {%0,%1,%2,%3};"
                 : "+f"(c[0]), "+f"(c[1]), "+f"(c[2]), "+f"(c[3])
                 : "r"(a[0]), "r"(a[1]), "r"(a[2]), "r"(a[3]), "r"(b[0]), "r"(b[1]));
}

__device__ __forceinline__ void split_pair(float x, float y, bf162& h, bf162& l) {
    h = __floats2bfloat162_rn(x, y);
    l = __floats2bfloat162_rn(x - __bfloat162float(h.x), y - __bfloat162float(h.y));
}

// ================= bf16 NT GEMM over pre-split K' =================
// D[m,n] = sum_k A[m,k]*B[n,k], A [M,Kp], B [N,Kp] bf16 row-major.
// MODE: 0=fp32 store; 1=A-split store (hi,lo,hi); 2=B-split store (hi,hi,lo);
//       3=bias+residual then A-split store.
#define GSMEM 65536   // 2 stages x (16KB A + 16KB B)

template <int MODE>
__global__ void __launch_bounds__(256, 2)
gemm_nt(const bf16* __restrict__ Ag, const bf16* __restrict__ Bg,
        void* __restrict__ Cg, int Kp, int ldc,
        long long sA, long long sB, long long sC,
        const float* __restrict__ bias, const float* __restrict__ res)
{
    extern __shared__ char smc[];
    const uint32_t sm0 = smem_u32(smc);
    const int tid  = threadIdx.x;
    const int wid  = tid >> 5;
    const int lane = tid & 31;
    const int wm = wid >> 2;        // 0..1
    const int wn = wid & 3;         // 0..3
    const int m0 = blockIdx.y * 128;
    const int n0 = blockIdx.x * 128;

    Ag += (long long)blockIdx.z * sA;
    Bg += (long long)blockIdx.z * sB;

    const bf16* Abase = Ag + (long long)m0 * Kp;
    const bf16* Bbase = Bg + (long long)n0 * Kp;

    // cp.async mapping: chunk ci in [0,1024): row=ci>>3, 16B col=ci&7
    const int crow = tid >> 3;          // base rows for i-strided chunks
    const int ccol = tid & 7;

    float acc[4][4][4];
    #pragma unroll
    for (int a = 0; a < 4; a++)
        #pragma unroll
        for (int b = 0; b < 4; b++)
            #pragma unroll
            for (int c = 0; c < 4; c++) acc[a][b][c] = 0.0f;

    const int KT = Kp >> 6;

    auto load_stage = [&](int st, int kt) {
        const uint32_t sa = sm0 + st * 32768;
        const uint32_t sb = sa + 16384;
        const int kofs = kt * 64;
        #pragma unroll
        for (int i = 0; i < 4; i++) {
            const int row = crow + i * 32;
            const uint32_t soff = SWZ128((uint32_t)(row * 128 + ccol * 16));
            cpa16(sa + soff, Abase + (long long)row * Kp + kofs + ccol * 8);
            cpa16(sb + soff, Bbase + (long long)row * Kp + kofs + ccol * 8);
        }
    };

    load_stage(0, 0); cpa_commit();
    load_stage(1, 1); cpa_commit();
    cpa_wait<1>();
    __syncthreads();

    for (int kt = 0; kt < KT; ++kt) {
        const uint32_t sa = sm0 + (kt & 1) * 32768;
        const uint32_t sb = sa + 16384;

        #pragma unroll
        for (int ks = 0; ks < 4; ks++) {
            uint32_t afr[4][4];
            uint32_t bfr[4][2];
            const int bcol = ks * 32 + ((lane >> 4) << 4);
            #pragma unroll
            for (int mt = 0; mt < 4; mt++) {
                const int row = wm * 64 + mt * 16 + (lane & 15);
                ldsm_x4(sa + SWZ128((uint32_t)(row * 128 + bcol)),
                        afr[mt][0], afr[mt][1], afr[mt][2], afr[mt][3]);
            }
            #pragma unroll
            for (int np = 0; np < 2; np++) {
                const int row = wn * 32 + np * 16 + (lane & 15);
                uint32_t r0, r1, r2, r3;
                ldsm_x4(sb + SWZ128((uint32_t)(row * 128 + bcol)), r0, r1, r2, r3);
                bfr[2*np][0] = r0;   bfr[2*np][1] = r2;
                bfr[2*np+1][0] = r1; bfr[2*np+1][1] = r3;
            }
            #pragma unroll
            for (int mt = 0; mt < 4; mt++)
                #pragma unroll
                for (int nt = 0; nt < 4; nt++)
                    mma16816(acc[mt][nt], afr[mt], bfr[nt]);
        }
        __syncthreads();
        if (kt + 2 < KT) load_stage(kt & 1, kt + 2);
        cpa_commit();
        cpa_wait<1>();
        __syncthreads();
    }

    // -------- epilogue --------
    const int ld3 = 3 * ldc;
    #pragma unroll
    for (int mt = 0; mt < 4; mt++) {
        #pragma unroll
        for (int nt = 0; nt < 4; nt++) {
            const int r0 = m0 + wm * 64 + mt * 16 + (lane >> 2);
            const int r1 = r0 + 8;
            const int c  = n0 + wn * 32 + nt * 8 + (lane & 3) * 2;
            float x0 = acc[mt][nt][0], y0 = acc[mt][nt][1];
            float x1 = acc[mt][nt][2], y1 = acc[mt][nt][3];
            if (MODE == 3) {
                const float2 bv = *(const float2*)&bias[c];
                const float2 q0 = *(const float2*)&res[(long long)r0 * ldc + c];
                const float2 q1 = *(const float2*)&res[(long long)r1 * ldc + c];
                x0 += bv.x + q0.x; y0 += bv.y + q0.y;
                x1 += bv.x + q1.x; y1 += bv.y + q1.y;
            }
            if (MODE == 0) {
                float* Cf = (float*)Cg + (long long)blockIdx.z * sC;
                *(float2*)&Cf[(long long)r0 * ldc + c] = make_float2(x0, y0);
                *(float2*)&Cf[(long long)r1 * ldc + c] = make_float2(x1, y1);
            } else {
                bf16* Cs = (bf16*)Cg + (long long)blockIdx.z * sC;
                bf162 h0, l0, h1, l1;
                split_pair(x0, y0, h0, l0);
                split_pair(x1, y1, h1, l1);
                bf16* p0 = Cs + (long long)r0 * ld3 + c;
                bf16* p1 = Cs + (long long)r1 * ld3 + c;
                if (MODE == 2) {            // B-split: hi, hi, lo
                    *(bf162*)(p0) = h0; *(bf162*)(p0 + ldc) = h0; *(bf162*)(p0 + 2*ldc) = l0;
                    *(bf162*)(p1) = h1; *(bf162*)(p1 + ldc) = h1; *(bf162*)(p1 + 2*ldc) = l1;
                } else {                    // A-split: hi, lo, hi
                    *(bf162*)(p0) = h0; *(bf162*)(p0 + ldc) = l0; *(bf162*)(p0 + 2*ldc) = h0;
                    *(bf162*)(p1) = h1; *(bf162*)(p1 + ldc) = l1; *(bf162*)(p1 + 2*ldc) = h1;
                }
            }
        }
    }
}

// ================= A-split elementwise: X[R,C] fp32 -> Y[R,3C] (hi,lo,hi) ========
__global__ void asplit_kernel(const float* __restrict__ X, bf16* __restrict__ Y, int C)
{
    const long long i4 = (long long)blockIdx.x * blockDim.x + threadIdx.x;
    const int c4 = C >> 2;
    const long long r = i4 / c4;
    const int cj = (int)(i4 - r * c4) * 4;
    float4 v = ((const float4*)X)[i4];
    bf162 h0, l0, h1, l1;
    split_pair(v.x, v.y, h0, l0);
    split_pair(v.z, v.w, h1, l1);
    bf162* yr = (bf162*)(Y + r * 3LL * C);
    const int j = cj >> 1;
    yr[j] = h0; yr[j + 1] = h1;
    yr[(C >> 1) + j] = l0; yr[(C >> 1) + j + 1] = l1;
    yr[C + j] = h0; yr[C + j + 1] = h1;
}

// ============ B-split + transpose: In[R,C] fp32 -> Out[C,3R] (hi,hi,lo) =========
__global__ void bsplit_tr(const float* __restrict__ In, bf16* __restrict__ Out,
                          int R, int C, long long sIn, long long sOut)
{
    In  += (long long)blockIdx.z * sIn;
    Out += (long long)blockIdx.z * sOut;
    __shared__ float t[32][33];
    const int bx = blockIdx.x * 32;   // C dim
    const int by = blockIdx.y * 32;   // R dim
    const int tx = threadIdx.x, ty = threadIdx.y;
    #pragma unroll
    for (int i = ty; i < 32; i += 8)
        t[i][tx] = In[(long long)(by + i) * C + bx + tx];
    __syncthreads();
    #pragma unroll
    for (int i = ty; i < 32; i += 8) {
        const float v = t[tx][i];
        const bf16 h = __float2bfloat16(v);
        const bf16 l = __float2bfloat16(v - __bfloat162float(h));
        const long long ro = (long long)(bx + i) * (3LL * R) + by + tx;
        Out[ro] = h; Out[ro + R] = h; Out[ro + 2LL * R] = l;
    }
}

// ================= reductions =================
__device__ __forceinline__ float blockReduceSum(float v, float* sh)
{
    const int t = threadIdx.x;
    #pragma unroll
    for (int o = 16; o; o >>= 1) v += __shfl_xor_sync(0xFFFFFFFFu, v, o);
    if ((t & 31) == 0) sh[t >> 5] = v;
    __syncthreads();
    if (t < 32) {
        float r = (t < 8) ? sh[t] : 0.0f;
        #pragma unroll
        for (int o = 4; o; o >>= 1) r += __shfl_xor_sync(0xFFFFFFFFu, r, o);
        if (t == 0) sh[0] = r;
    }
    __syncthreads();
    float r = sh[0];
    __syncthreads();
    return r;
}
__device__ __forceinline__ float blockReduceMax(float v, float* sh)
{
    const int t = threadIdx.x;
    #pragma unroll
    for (int o = 16; o; o >>= 1) v = fmaxf(v, __shfl_xor_sync(0xFFFFFFFFu, v, o));
    if ((t & 31) == 0) sh[t >> 5] = v;
    __syncthreads();
    if (t < 32) {
        float r = (t < 8) ? sh[t] : -1e30f;
        #pragma unroll
        for (int o = 4; o; o >>= 1) r = fmaxf(r, __shfl_xor_sync(0xFFFFFFFFu, r, o));
        if (t == 0) sh[0] = r;
    }
    __syncthreads();
    float r = sh[0];
    __syncthreads();
    return r;
}

// ===== softmax over a 4096 row + A-split bf16 output (hi,lo,hi) =====
__global__ void softmax_split_kernel(const float* __restrict__ S,
                                     bf16* __restrict__ Ss, float scale)
{
    const long long row = blockIdx.x;
    const float4* p = (const float4*)(S + row * SKV);
    __shared__ float buf[SKV];
    __shared__ float red[32];
    float4* b4 = (float4*)buf;
    const int t = threadIdx.x;

    float m = -1e30f;
    #pragma unroll
    for (int i = 0; i < 4; i++) {
        float4 v = p[t + 256 * i];
        b4[t + 256 * i] = v;
        m = fmaxf(m, fmaxf(fmaxf(v.x, v.y), fmaxf(v.z, v.w)));
    }
    m = blockReduceMax(m, red);

    float sum = 0.0f;
    #pragma unroll
    for (int i = 0; i < 4; i++) {
        float4 v = b4[t + 256 * i];
        v.x = __expf((v.x - m) * scale); v.y = __expf((v.y - m) * scale);
        v.z = __expf((v.z - m) * scale); v.w = __expf((v.w - m) * scale);
        sum += v.x + v.y + v.z + v.w;
        b4[t + 256 * i] = v;
    }
    sum = blockReduceSum(sum, red);
    const float rinv = 1.0f / sum;

    bf162* o = (bf162*)(Ss + row * 3LL * SKV);
    #pragma unroll
    for (int i = 0; i < 4; i++) {
        float4 v = b4[t + 256 * i];
        bf162 h0, l0, h1, l1;
        split_pair(v.x * rinv, v.y * rinv, h0, l0);
        split_pair(v.z * rinv, v.w * rinv, h1, l1);
        const int j = (t + 256 * i) * 2;
        o[j] = h0; o[j + 1] = h1;
        o[(SKV >> 1) + j] = l0; o[(SKV >> 1) + j + 1] = l1;
        o[SKV + j] = h0; o[SKV + j + 1] = h1;
    }
}

// ================= layernorm =================
__global__ void layernorm_kernel(const float* __restrict__ X,
                                 const float* __restrict__ gamma,
                                 const float* __restrict__ beta,
                                 float* __restrict__ Y)
{
    const float* x = X + (long long)blockIdx.x * EMBED;
    float*       y = Y + (long long)blockIdx.x * EMBED;
    const int t = threadIdx.x;
    __shared__ float sh[32];

    float4 v = *(const float4*)&x[t * 4];
    float s = v.x + v.y + v.z + v.w;
    s = blockReduceSum(s, sh);
    const float mu = s * (1.0f / EMBED);

    float dx = v.x - mu, dy = v.y - mu, dz = v.z - mu, dw = v.w - mu;
    float sq = dx * dx + dy * dy + dz * dz + dw * dw;
    sq = blockReduceSum(sq, sh);
    const float rstd = rsqrtf(sq * (1.0f / EMBED) + 1e-5f);

    float4 g = *(const float4*)&gamma[t * 4];
    float4 b = *(const float4*)&beta[t * 4];
    float4 o;
    o.x = dx * rstd * g.x + b.x;
    o.y = dy * rstd * g.y + b.y;
    o.z = dz * rstd * g.z + b.z;
    o.w = dw * rstd * g.w + b.w;
    *(float4*)&y[t * 4] = o;
}

// ================= launch =================
extern "C" void kernel_launch(void* const* d_in, const int* in_sizes, int n_in,
                              void* d_out, int out_size)
{
    const float* q_feat = (const float*)d_in[0];
    const float* kv     = (const float*)d_in[1];
    const float* Wq     = (const float*)d_in[2];
    const float* Wk     = (const float*)d_in[3];
    const float* Wv     = (const float*)d_in[4];
    const float* Wo     = (const float*)d_in[5];
    const float* bo     = (const float*)d_in[6];
    const float* Wfc    = (const float*)d_in[7];
    const float* gamma  = (const float*)d_in[8];
    const float* beta   = (const float*)d_in[9];
    float* out = (float*)d_out;

    float *V, *S, *O2;
    bf16 *qs, *kvs, *Qs, *Ks, *VTs, *Ss, *Cs, *O1s;
    bf16 *WqTs, *WkTs, *WvTs, *WoTs, *WfcTs;
    cudaGetSymbolAddress((void**)&V,    g_V);
    cudaGetSymbolAddress((void**)&S,    g_S);
    cudaGetSymbolAddress((void**)&O2,   g_O2);
    cudaGetSymbolAddress((void**)&qs,   g_qs);
    cudaGetSymbolAddress((void**)&kvs,  g_kvs);
    cudaGetSymbolAddress((void**)&Qs,   g_Qs);
    cudaGetSymbolAddress((void**)&Ks,   g_Ks);
    cudaGetSymbolAddress((void**)&VTs,  g_VTs);
    cudaGetSymbolAddress((void**)&Ss,   g_Ss);
    cudaGetSymbolAddress((void**)&Cs,   g_Cs);
    cudaGetSymbolAddress((void**)&O1s,  g_O1s);
    cudaGetSymbolAddress((void**)&WqTs, g_WqTs);
    cudaGetSymbolAddress((void**)&WkTs, g_WkTs);
    cudaGetSymbolAddress((void**)&WvTs, g_WvTs);
    cudaGetSymbolAddress((void**)&WoTs, g_WoTs);
    cudaGetSymbolAddress((void**)&WfcTs, g_WfcTs);

    cudaFuncSetAttribute(gemm_nt<0>, cudaFuncAttributeMaxDynamicSharedMemorySize, GSMEM);
    cudaFuncSetAttribute(gemm_nt<1>, cudaFuncAttributeMaxDynamicSharedMemorySize, GSMEM);
    cudaFuncSetAttribute(gemm_nt<2>, cudaFuncAttributeMaxDynamicSharedMemorySize, GSMEM);
    cudaFuncSetAttribute(gemm_nt<3>, cudaFuncAttributeMaxDynamicSharedMemorySize, GSMEM);

    const dim3 blk(256);
    const dim3 tblk(32, 8);
    const float scale = 0.044194173824159216f;  // 1/sqrt(512)

    // ---- operand preparation ----
    // weights: W[in,out] -> B-split of W^T
    bsplit_tr<<<dim3(HIDDEN/32, EMBED/32, 1), tblk>>>(Wq,  WqTs,  EMBED, HIDDEN, 0, 0);
    bsplit_tr<<<dim3(HIDDEN/32, EMBED/32, 1), tblk>>>(Wk,  WkTs,  EMBED, HIDDEN, 0, 0);
    bsplit_tr<<<dim3(HIDDEN/32, EMBED/32, 1), tblk>>>(Wv,  WvTs,  EMBED, HIDDEN, 0, 0);
    bsplit_tr<<<dim3(EMBED/32, HIDDEN/32, 1), tblk>>>(Wo,  WoTs,  HIDDEN, EMBED, 0, 0);
    bsplit_tr<<<dim3(EMBED/32, EMBED/32, 1),  tblk>>>(Wfc, WfcTs, EMBED, EMBED, 0, 0);
    // activations: A-split
    asplit_kernel<<<(MTOK * EMBED / 4) / 256, 256>>>(q_feat, qs, EMBED);
    asplit_kernel<<<(MTOK * EMBED / 4) / 256, 256>>>(kv, kvs, EMBED);

    const int K3E = 3 * EMBED;   // 3072
    const int K3H = 3 * HIDDEN;  // 1536
    const int K3S = 3 * SQ;      // 12288

    // Q = qf @ Wq  (A-split out)
    gemm_nt<1><<<dim3(HIDDEN/128, MTOK/128, 1), blk, GSMEM>>>(
        qs, WqTs, Qs, K3E, HIDDEN, 0, 0, 0, nullptr, nullptr);
    // K = kv @ Wk  (B-split out)
    gemm_nt<2><<<dim3(HIDDEN/128, MTOK/128, 1), blk, GSMEM>>>(
        kvs, WkTs, Ks, K3E, HIDDEN, 0, 0, 0, nullptr, nullptr);
    // V = kv @ Wv  (fp32 out)
    gemm_nt<0><<<dim3(HIDDEN/128, MTOK/128, 1), blk, GSMEM>>>(
        kvs, WvTs, V, K3E, HIDDEN, 0, 0, 0, nullptr, nullptr);
    // VT B-split per batch: V[b] [4096,512] -> VTs[b] [512, 12288]
    bsplit_tr<<<dim3(HIDDEN/32, SQ/32, NB), tblk>>>(
        V, VTs, SQ, HIDDEN, (long long)SQ * HIDDEN, (long long)HIDDEN * K3S);

    // scores = Q @ K^T per batch (fp32 out)
    gemm_nt<0><<<dim3(SKV/128, SQ/128, NB), blk, GSMEM>>>(
        Qs, Ks, S, K3H, SKV,
        (long long)SQ * K3H, (long long)SKV * K3H, (long long)SQ * SKV,
        nullptr, nullptr);

    // softmax + A-split probs
    softmax_split_kernel<<<NB * SQ, 256>>>(S, Ss, scale);

    // ctx = P @ V per batch (A-split out into Cs rows)
    gemm_nt<1><<<dim3(HIDDEN/128, SQ/128, NB), blk, GSMEM>>>(
        Ss, VTs, Cs, K3S, HIDDEN,
        (long long)SQ * K3S, (long long)HIDDEN * K3S, (long long)SQ * K3H,
        nullptr, nullptr);

    // O1 = ctx @ Wo + bo + q_feat (A-split out)
    gemm_nt<3><<<dim3(EMBED/128, MTOK/128, 1), blk, GSMEM>>>(
        Cs, WoTs, O1s, K3H, EMBED, 0, 0, 0, bo, q_feat);

    // O2 = O1 @ Wfc (fp32 out)
    gemm_nt<0><<<dim3(EMBED/128, MTOK/128, 1), blk, GSMEM>>>(
        O1s, WfcTs, O2, K3E, EMBED, 0, 0, 0, nullptr, nullptr);

    layernorm_kernel<<<MTOK, 256>>>(O2, gamma, beta, out);
}

// round 4
// speedup vs baseline: 7.2341x; 1.7894x over previous
#include <cuda_runtime.h>
#include <cuda_bf16.h>
#include <cstdint>
#include <math.h>

#define EMBED  1024
#define HIDDEN 512
#define NB     4
#define SQ     4096
#define SKV    4096
#define MTOK   (NB * SQ)   // 16384

typedef __nv_bfloat16 bf16;
typedef __nv_bfloat162 bf162;

// ---------------- scratch (static device arrays; no allocations) ----------------
__device__ bf16 g_qs  [(size_t)MTOK * 3 * EMBED];    // A-split q_feat [hi|lo|hi]
__device__ bf16 g_kvs [(size_t)MTOK * 3 * EMBED];    // A-split kv_feat
__device__ bf16 g_Qh  [(size_t)MTOK * HIDDEN];       // plain bf16 Q
__device__ bf16 g_Kh  [(size_t)MTOK * HIDDEN];       // plain bf16 K
__device__ bf16 g_VT  [(size_t)HIDDEN * MTOK];       // plain bf16 V^T [H, tokens]
__device__ bf16 g_S   [(size_t)NB * SQ * SKV];       // unnormalized exp-scores (bf16)
__device__ float g_Zi [MTOK];                        // 1/rowsum
__device__ bf16 g_Ch  [(size_t)MTOK * HIDDEN];       // plain bf16 ctx
__device__ bf16 g_O1s [(size_t)MTOK * 3 * EMBED];    // A-split O1
__device__ float g_O2 [(size_t)MTOK * EMBED];        // fp32 pre-LN
__device__ bf16 g_Wq3 [(size_t)HIDDEN * 3 * EMBED];  // B-split x3 Wq^T [hi|hi|lo]
__device__ bf16 g_Wk3 [(size_t)HIDDEN * 3 * EMBED];
__device__ bf16 g_Wv2 [(size_t)HIDDEN * 2 * EMBED];  // [hi|lo] Wv^T (hi used)
__device__ bf16 g_Wo2 [(size_t)EMBED * 2 * HIDDEN];  // [hi|lo] Wo^T (hi used)
__device__ bf16 g_Wfc3[(size_t)EMBED * 3 * EMBED];   // B-split x3 Wfc^T

// ================= helpers =================
__device__ __forceinline__ uint32_t smem_u32(const void* p) {
    return (uint32_t)__cvta_generic_to_shared((void*)p);
}
#define SWZ128(o) ((o) ^ (((o) >> 3) & 0x70))

__device__ __forceinline__ void cpa16(uint32_t s, const void* g) {
    asm volatile("cp.async.cg.shared.global [%0], [%1], 16;" :: "r"(s), "l"(g));
}
__device__ __forceinline__ void cpa_commit() {
    asm volatile("cp.async.commit_group;" ::: "memory");
}
template <int N> __device__ __forceinline__ void cpa_wait() {
    asm volatile("cp.async.wait_group %0;" :: "n"(N) : "memory");
}
__device__ __forceinline__ void ldsm_x4(uint32_t a, uint32_t& r0, uint32_t& r1,
                                        uint32_t& r2, uint32_t& r3) {
    asm volatile("ldmatrix.sync.aligned.m8n8.x4.shared.b16 {%0,%1,%2,%3}, [%4];"
                 : "=r"(r0), "=r"(r1), "=r"(r2), "=r"(r3) : "r"(a));
}
__device__ __forceinline__ void mma16816(float* c, const uint32_t* a, const uint32_t* b) {
    asm volatile("mma.sync.aligned.m16n8k16.row.col.f32.bf16.bf16.f32 "
                 "{%0,%1,%2,%3}, {%4,%5,%6,%7}, {%8,%9}, {%0,%1,%2,%3};"
                 : "+f"(c[0]), "+f"(c[1]), "+f"(c[2]), "+f"(c[3])
                 : "r"(a[0]), "r"(a[1]), "r"(a[2]), "r"(a[3]), "r"(b[0]), "r"(b[1]));
}
__device__ __forceinline__ void split_pair(float x, float y, bf162& h, bf162& l) {
    h = __floats2bfloat162_rn(x, y);
    l = __floats2bfloat162_rn(x - __bfloat162float(h.x), y - __bfloat162float(h.y));
}

// 2^t : MUFU path and fp32-poly path (deg-5 Taylor on fraction, rel err ~1e-4)
__device__ __forceinline__ float ex2_mufu(float t) {
    float r;
    asm("ex2.approx.f32 %0, %1;" : "=f"(r) : "f"(t));
    return r;
}
__device__ __forceinline__ float ex2_poly(float t) {
    float fl = floorf(t);
    float f  = t - fl;
    int   i  = (int)fl;
    float p = fmaf(f, 0.0013333558f, 0.0096181291f);
    p = fmaf(f, p, 0.0555041087f);
    p = fmaf(f, p, 0.2402264923f);
    p = fmaf(f, p, 0.6931471806f);
    p = fmaf(f, p, 1.0f);
    return __int_as_float((i + 127) << 23) * p;
}

// ================= bf16 NT GEMM =================
// D[m,n] = sum_k A[m,k]*B[n,k]; A row-stride lda, B row-stride ldb (bf16, rm).
// MODE 0: fp32 store
// MODE 3: +bias[col]+res[row,col] (fp32) -> A-split x3 bf16 store [hi|lo|hi]
// MODE 4: plain bf16 store
// MODE 5: acc * rowscale[z*sAux + r] -> plain bf16 store
// MODE 6: exp2(acc * escale2) (mixed mufu/poly) -> plain bf16 store
#define GSMEM 65536   // 2 stages x (16KB A + 16KB B)

template <int MODE>
__global__ void __launch_bounds__(256, 2)
gemm_nt(const bf16* __restrict__ Ag, const bf16* __restrict__ Bg,
        void* __restrict__ Cg, int Kp, int lda, int ldb, int ldc,
        long long sA, long long sB, long long sC,
        const float* __restrict__ aux1, const float* __restrict__ aux2,
        long long sAux, float escale2)
{
    extern __shared__ char smc[];
    const uint32_t sm0 = smem_u32(smc);
    const int tid  = threadIdx.x;
    const int wid  = tid >> 5;
    const int lane = tid & 31;
    const int wm = wid >> 2;        // 0..1
    const int wn = wid & 3;         // 0..3
    const int m0 = blockIdx.y * 128;
    const int n0 = blockIdx.x * 128;

    Ag += (long long)blockIdx.z * sA;
    Bg += (long long)blockIdx.z * sB;

    const bf16* Abase = Ag + (long long)m0 * lda;
    const bf16* Bbase = Bg + (long long)n0 * ldb;

    const int crow = tid >> 3;          // 0..31 base row
    const int ccol = tid & 7;           // 16B chunk

    float acc[4][4][4];
    #pragma unroll
    for (int a = 0; a < 4; a++)
        #pragma unroll
        for (int b = 0; b < 4; b++)
            #pragma unroll
            for (int c = 0; c < 4; c++) acc[a][b][c] = 0.0f;

    const int KT = Kp >> 6;

    auto load_stage = [&](int st, int kt) {
        const uint32_t sa = sm0 + st * 32768;
        const uint32_t sb = sa + 16384;
        const int kofs = kt * 64;
        #pragma unroll
        for (int i = 0; i < 4; i++) {
            const int row = crow + i * 32;
            const uint32_t soff = SWZ128((uint32_t)(row * 128 + ccol * 16));
            cpa16(sa + soff, Abase + (long long)row * lda + kofs + ccol * 8);
            cpa16(sb + soff, Bbase + (long long)row * ldb + kofs + ccol * 8);
        }
    };

    load_stage(0, 0); cpa_commit();
    load_stage(1, 1); cpa_commit();
    cpa_wait<1>();
    __syncthreads();

    for (int kt = 0; kt < KT; ++kt) {
        const uint32_t sa = sm0 + (kt & 1) * 32768;
        const uint32_t sb = sa + 16384;

        #pragma unroll
        for (int ks = 0; ks < 4; ks++) {
            uint32_t afr[4][4];
            uint32_t bfr[4][2];
            const int bcol = ks * 32 + ((lane >> 4) << 4);
            #pragma unroll
            for (int mt = 0; mt < 4; mt++) {
                const int row = wm * 64 + mt * 16 + (lane & 15);
                ldsm_x4(sa + SWZ128((uint32_t)(row * 128 + bcol)),
                        afr[mt][0], afr[mt][1], afr[mt][2], afr[mt][3]);
            }
            #pragma unroll
            for (int np = 0; np < 2; np++) {
                const int row = wn * 32 + np * 16 + (lane & 15);
                uint32_t r0, r1, r2, r3;
                ldsm_x4(sb + SWZ128((uint32_t)(row * 128 + bcol)), r0, r1, r2, r3);
                bfr[2*np][0] = r0;   bfr[2*np][1] = r2;
                bfr[2*np+1][0] = r1; bfr[2*np+1][1] = r3;
            }
            #pragma unroll
            for (int mt = 0; mt < 4; mt++)
                #pragma unroll
                for (int nt = 0; nt < 4; nt++)
                    mma16816(acc[mt][nt], afr[mt], bfr[nt]);
        }
        __syncthreads();
        if (kt + 2 < KT) load_stage(kt & 1, kt + 2);
        cpa_commit();
        cpa_wait<1>();
        __syncthreads();
    }

    // -------- epilogue --------
    const int ld3 = 3 * ldc;
    const float* rs = (MODE == 5) ? (aux1 + (long long)blockIdx.z * sAux) : nullptr;

    #pragma unroll
    for (int mt = 0; mt < 4; mt++) {
        const int r0 = m0 + wm * 64 + mt * 16 + (lane >> 2);
        const int r1 = r0 + 8;
        float rs0 = 1.0f, rs1 = 1.0f;
        if (MODE == 5) { rs0 = rs[r0]; rs1 = rs[r1]; }
        #pragma unroll
        for (int nt = 0; nt < 4; nt++) {
            const int c = n0 + wn * 32 + nt * 8 + (lane & 3) * 2;
            float x0 = acc[mt][nt][0], y0 = acc[mt][nt][1];
            float x1 = acc[mt][nt][2], y1 = acc[mt][nt][3];
            if (MODE == 5) { x0 *= rs0; y0 *= rs0; x1 *= rs1; y1 *= rs1; }
            if (MODE == 6) {
                if (nt & 1) {
                    x0 = ex2_mufu(x0 * escale2); y0 = ex2_mufu(y0 * escale2);
                    x1 = ex2_mufu(x1 * escale2); y1 = ex2_mufu(y1 * escale2);
                } else {
                    x0 = ex2_poly(x0 * escale2); y0 = ex2_poly(y0 * escale2);
                    x1 = ex2_poly(x1 * escale2); y1 = ex2_poly(y1 * escale2);
                }
            }
            if (MODE == 3) {
                const float2 bv = *(const float2*)&aux1[c];
                const float2 q0 = *(const float2*)&aux2[(long long)r0 * ldc + c];
                const float2 q1 = *(const float2*)&aux2[(long long)r1 * ldc + c];
                x0 += bv.x + q0.x; y0 += bv.y + q0.y;
                x1 += bv.x + q1.x; y1 += bv.y + q1.y;
                bf16* Cs = (bf16*)Cg;
                bf162 h0, l0, h1, l1;
                split_pair(x0, y0, h0, l0);
                split_pair(x1, y1, h1, l1);
                bf16* p0 = Cs + (long long)r0 * ld3 + c;
                bf16* p1 = Cs + (long long)r1 * ld3 + c;
                *(bf162*)(p0) = h0; *(bf162*)(p0 + ldc) = l0; *(bf162*)(p0 + 2*ldc) = h0;
                *(bf162*)(p1) = h1; *(bf162*)(p1 + ldc) = l1; *(bf162*)(p1 + 2*ldc) = h1;
            } else if (MODE == 0) {
                float* Cf = (float*)Cg + (long long)blockIdx.z * sC;
                *(float2*)&Cf[(long long)r0 * ldc + c] = make_float2(x0, y0);
                *(float2*)&Cf[(long long)r1 * ldc + c] = make_float2(x1, y1);
            } else {
                bf16* Cb = (bf16*)Cg + (long long)blockIdx.z * sC;
                *(bf162*)&Cb[(long long)r0 * ldc + c] = __floats2bfloat162_rn(x0, y0);
                *(bf162*)&Cb[(long long)r1 * ldc + c] = __floats2bfloat162_rn(x1, y1);
            }
        }
    }
}

// ================= A-split elementwise: X[R,C] fp32 -> Y[R,3C] (hi,lo,hi) ========
__global__ void asplit_kernel(const float* __restrict__ X, bf16* __restrict__ Y, int C)
{
    const long long i4 = (long long)blockIdx.x * blockDim.x + threadIdx.x;
    const int c4 = C >> 2;
    const long long r = i4 / c4;
    const int cj = (int)(i4 - r * c4) * 4;
    float4 v = ((const float4*)X)[i4];
    bf162 h0, l0, h1, l1;
    split_pair(v.x, v.y, h0, l0);
    split_pair(v.z, v.w, h1, l1);
    bf162* yr = (bf162*)(Y + r * 3LL * C);
    const int j = cj >> 1;
    yr[j] = h0; yr[j + 1] = h1;
    yr[(C >> 1) + j] = l0; yr[(C >> 1) + j + 1] = l1;
    yr[C + j] = h0; yr[C + j + 1] = h1;
}

// ============ B-split x3 + transpose: In[R,C] fp32 -> Out[C,3R] (hi,hi,lo) =======
__global__ void bsplit3_tr(const float* __restrict__ In, bf16* __restrict__ Out,
                           int R, int C)
{
    __shared__ float t[32][33];
    const int bx = blockIdx.x * 32;
    const int by = blockIdx.y * 32;
    const int tx = threadIdx.x, ty = threadIdx.y;
    #pragma unroll
    for (int i = ty; i < 32; i += 8)
        t[i][tx] = In[(long long)(by + i) * C + bx + tx];
    __syncthreads();
    #pragma unroll
    for (int i = ty; i < 32; i += 8) {
        const float v = t[tx][i];
        const bf16 h = __float2bfloat16(v);
        const bf16 l = __float2bfloat16(v - __bfloat162float(h));
        const long long ro = (long long)(bx + i) * (3LL * R) + by + tx;
        Out[ro] = h; Out[ro + R] = h; Out[ro + 2LL * R] = l;
    }
}

// ============ B-split x2 + transpose: In[R,C] fp32 -> Out[C,2R] (hi,lo) ==========
__global__ void bsplit2_tr(const float* __restrict__ In, bf16* __restrict__ Out,
                           int R, int C)
{
    __shared__ float t[32][33];
    const int bx = blockIdx.x * 32;
    const int by = blockIdx.y * 32;
    const int tx = threadIdx.x, ty = threadIdx.y;
    #pragma unroll
    for (int i = ty; i < 32; i += 8)
        t[i][tx] = In[(long long)(by + i) * C + bx + tx];
    __syncthreads();
    #pragma unroll
    for (int i = ty; i < 32; i += 8) {
        const float v = t[tx][i];
        const bf16 h = __float2bfloat16(v);
        const bf16 l = __float2bfloat16(v - __bfloat162float(h));
        const long long ro = (long long)(bx + i) * (2LL * R) + by + tx;
        Out[ro] = h; Out[ro + R] = l;
    }
}

// ================= reductions =================
__device__ __forceinline__ float blockReduceSum(float v, float* sh)
{
    const int t = threadIdx.x;
    #pragma unroll
    for (int o = 16; o; o >>= 1) v += __shfl_xor_sync(0xFFFFFFFFu, v, o);
    if ((t & 31) == 0) sh[t >> 5] = v;
    __syncthreads();
    if (t < 32) {
        float r = (t < 8) ? sh[t] : 0.0f;
        #pragma unroll
        for (int o = 4; o; o >>= 1) r += __shfl_xor_sync(0xFFFFFFFFu, r, o);
        if (t == 0) sh[0] = r;
    }
    __syncthreads();
    float r = sh[0];
    __syncthreads();
    return r;
}

// ===== row sums of unnormalized exp-scores -> Zinv =====
__global__ void sumexp_kernel(const bf16* __restrict__ S, float* __restrict__ Zi)
{
    const bf162* p = (const bf162*)(S + (long long)blockIdx.x * SKV);
    const int t = threadIdx.x;
    __shared__ float sh[32];
    float s = 0.0f;
    #pragma unroll
    for (int i = 0; i < 8; i++) {
        float2 v = __bfloat1622float2(p[t + 256 * i]);
        s += v.x + v.y;
    }
    s = blockReduceSum(s, sh);
    if (t == 0) Zi[blockIdx.x] = 1.0f / s;
}

// ================= layernorm =================
__global__ void layernorm_kernel(const float* __restrict__ X,
                                 const float* __restrict__ gamma,
                                 const float* __restrict__ beta,
                                 float* __restrict__ Y)
{
    const float* x = X + (long long)blockIdx.x * EMBED;
    float*       y = Y + (long long)blockIdx.x * EMBED;
    const int t = threadIdx.x;
    __shared__ float sh[32];

    float4 v = *(const float4*)&x[t * 4];
    float s = v.x + v.y + v.z + v.w;
    s = blockReduceSum(s, sh);
    const float mu = s * (1.0f / EMBED);

    float dx = v.x - mu, dy = v.y - mu, dz = v.z - mu, dw = v.w - mu;
    float sq = dx * dx + dy * dy + dz * dz + dw * dw;
    sq = blockReduceSum(sq, sh);
    const float rstd = rsqrtf(sq * (1.0f / EMBED) + 1e-5f);

    float4 g = *(const float4*)&gamma[t * 4];
    float4 b = *(const float4*)&beta[t * 4];
    float4 o;
    o.x = dx * rstd * g.x + b.x;
    o.y = dy * rstd * g.y + b.y;
    o.z = dz * rstd * g.z + b.z;
    o.w = dw * rstd * g.w + b.w;
    *(float4*)&y[t * 4] = o;
}

// ================= launch =================
extern "C" void kernel_launch(void* const* d_in, const int* in_sizes, int n_in,
                              void* d_out, int out_size)
{
    const float* q_feat = (const float*)d_in[0];
    const float* kv     = (const float*)d_in[1];
    const float* Wq     = (const float*)d_in[2];
    const float* Wk     = (const float*)d_in[3];
    const float* Wv     = (const float*)d_in[4];
    const float* Wo     = (const float*)d_in[5];
    const float* bo     = (const float*)d_in[6];
    const float* Wfc    = (const float*)d_in[7];
    const float* gamma  = (const float*)d_in[8];
    const float* beta   = (const float*)d_in[9];
    float* out = (float*)d_out;

    bf16 *qs, *kvs, *Qh, *Kh, *VT, *S, *Ch, *O1s, *Wq3, *Wk3, *Wv2, *Wo2, *Wfc3;
    float *Zi, *O2;
    cudaGetSymbolAddress((void**)&qs,   g_qs);
    cudaGetSymbolAddress((void**)&kvs,  g_kvs);
    cudaGetSymbolAddress((void**)&Qh,   g_Qh);
    cudaGetSymbolAddress((void**)&Kh,   g_Kh);
    cudaGetSymbolAddress((void**)&VT,   g_VT);
    cudaGetSymbolAddress((void**)&S,    g_S);
    cudaGetSymbolAddress((void**)&Zi,   g_Zi);
    cudaGetSymbolAddress((void**)&Ch,   g_Ch);
    cudaGetSymbolAddress((void**)&O1s,  g_O1s);
    cudaGetSymbolAddress((void**)&O2,   g_O2);
    cudaGetSymbolAddress((void**)&Wq3,  g_Wq3);
    cudaGetSymbolAddress((void**)&Wk3,  g_Wk3);
    cudaGetSymbolAddress((void**)&Wv2,  g_Wv2);
    cudaGetSymbolAddress((void**)&Wo2,  g_Wo2);
    cudaGetSymbolAddress((void**)&Wfc3, g_Wfc3);

    cudaFuncSetAttribute(gemm_nt<0>, cudaFuncAttributeMaxDynamicSharedMemorySize, GSMEM);
    cudaFuncSetAttribute(gemm_nt<3>, cudaFuncAttributeMaxDynamicSharedMemorySize, GSMEM);
    cudaFuncSetAttribute(gemm_nt<4>, cudaFuncAttributeMaxDynamicSharedMemorySize, GSMEM);
    cudaFuncSetAttribute(gemm_nt<5>, cudaFuncAttributeMaxDynamicSharedMemorySize, GSMEM);
    cudaFuncSetAttribute(gemm_nt<6>, cudaFuncAttributeMaxDynamicSharedMemorySize, GSMEM);

    const dim3 blk(256);
    const dim3 tblk(32, 8);
    // exp(s/sqrt(512)) = 2^(s * escale2)
    const float escale2 = 0.044194173824159216f * 1.4426950408889634f;

    // ---- prep ----
    asplit_kernel<<<(MTOK * EMBED / 4) / 256, 256>>>(q_feat, qs, EMBED);
    asplit_kernel<<<(MTOK * EMBED / 4) / 256, 256>>>(kv, kvs, EMBED);
    bsplit3_tr<<<dim3(HIDDEN/32, EMBED/32), tblk>>>(Wq,  Wq3,  EMBED, HIDDEN);
    bsplit3_tr<<<dim3(HIDDEN/32, EMBED/32), tblk>>>(Wk,  Wk3,  EMBED, HIDDEN);
    bsplit2_tr<<<dim3(HIDDEN/32, EMBED/32), tblk>>>(Wv,  Wv2,  EMBED, HIDDEN);
    bsplit2_tr<<<dim3(EMBED/32, HIDDEN/32), tblk>>>(Wo,  Wo2,  HIDDEN, EMBED);
    bsplit3_tr<<<dim3(EMBED/32, EMBED/32),  tblk>>>(Wfc, Wfc3, EMBED, EMBED);

    // Q = qf @ Wq (x3) -> plain bf16
    gemm_nt<4><<<dim3(HIDDEN/128, MTOK/128, 1), blk, GSMEM>>>(
        qs, Wq3, Qh, 3*EMBED, 3*EMBED, 3*EMBED, HIDDEN,
        0, 0, 0, nullptr, nullptr, 0, 0.f);
    // K = kv @ Wk (x3) -> plain bf16
    gemm_nt<4><<<dim3(HIDDEN/128, MTOK/128, 1), blk, GSMEM>>>(
        kvs, Wk3, Kh, 3*EMBED, 3*EMBED, 3*EMBED, HIDDEN,
        0, 0, 0, nullptr, nullptr, 0, 0.f);
    // VT[h,t] = sum_e WvT_hi[h,e] * kv_hi[t,e]  (x1) -> plain bf16 [H, MTOK]
    gemm_nt<4><<<dim3(MTOK/128, HIDDEN/128, 1), blk, GSMEM>>>(
        Wv2, kvs, VT, EMBED, 2*EMBED, 3*EMBED, MTOK,
        0, 0, 0, nullptr, nullptr, 0, 0.f);

    // S = exp2(Q K^T * escale2) per batch (x1, exp fused) -> bf16
    gemm_nt<6><<<dim3(SKV/128, SQ/128, NB), blk, GSMEM>>>(
        Qh, Kh, S, HIDDEN, HIDDEN, HIDDEN, SKV,
        (long long)SQ * HIDDEN, (long long)SKV * HIDDEN, (long long)SQ * SKV,
        nullptr, nullptr, 0, escale2);

    // row sums -> Zinv
    sumexp_kernel<<<MTOK, 256>>>(S, Zi);

    // ctx = (S @ V) * Zinv per batch (x1) -> plain bf16
    gemm_nt<5><<<dim3(HIDDEN/128, SQ/128, NB), blk, GSMEM>>>(
        S, VT, Ch, SKV, SKV, MTOK, HIDDEN,
        (long long)SQ * SKV, (long long)SQ, (long long)SQ * HIDDEN,
        Zi, nullptr, SQ, 0.f);

    // O1 = ctx @ Wo_hi + bo + q_feat (x1) -> A-split x3
    gemm_nt<3><<<dim3(EMBED/128, MTOK/128, 1), blk, GSMEM>>>(
        Ch, Wo2, O1s, HIDDEN, HIDDEN, 2*HIDDEN, EMBED,
        0, 0, 0, bo, q_feat, 0, 0.f);

    // O2 = O1 @ Wfc (x3) -> fp32
    gemm_nt<0><<<dim3(EMBED/128, MTOK/128, 1), blk, GSMEM>>>(
        O1s, Wfc3, O2, 3*EMBED, 3*EMBED, 3*EMBED, EMBED,
        0, 0, 0, nullptr, nullptr, 0, 0.f);

    layernorm_kernel<<<MTOK, 256>>>(O2, gamma, beta, out);
}

// round 5
// speedup vs baseline: 8.7491x; 1.2094x over previous
#include <cuda_runtime.h>
#include <cuda_bf16.h>
#include <cstdint>
#include <math.h>

#define EMBED  1024
#define HIDDEN 512
#define NB     4
#define SQ     4096
#define SKV    4096
#define MTOK   (NB * SQ)   // 16384

typedef __nv_bfloat16 bf16;
typedef __nv_bfloat162 bf162;

// ---------------- scratch (static device arrays; no allocations) ----------------
__device__ bf16 g_qfh [(size_t)MTOK * EMBED];        // bf16 q_feat (hi)
__device__ bf16 g_kvh [(size_t)MTOK * EMBED];        // bf16 kv_feat (hi)
__device__ bf16 g_Qh  [(size_t)MTOK * HIDDEN];       // bf16 Q
__device__ bf16 g_Kh  [(size_t)MTOK * HIDDEN];       // bf16 K
__device__ bf16 g_VT  [(size_t)HIDDEN * MTOK];       // bf16 V^T [H, tokens]
__device__ bf16 g_S   [(size_t)NB * SQ * SKV];       // unnormalized exp-scores
__device__ float g_Zi [MTOK];                        // 1/rowsum
__device__ bf16 g_Ch  [(size_t)MTOK * HIDDEN];       // bf16 ctx
__device__ bf16 g_O1s [(size_t)MTOK * 3 * EMBED];    // A-split O1 [hi|lo|hi]
__device__ float g_O2 [(size_t)MTOK * EMBED];        // fp32 pre-LN
__device__ bf16 g_Wq1 [(size_t)HIDDEN * EMBED];      // bf16 Wq^T hi
__device__ bf16 g_Wk1 [(size_t)HIDDEN * EMBED];
__device__ bf16 g_Wv1 [(size_t)HIDDEN * EMBED];
__device__ bf16 g_Wo1 [(size_t)EMBED * HIDDEN];      // bf16 Wo^T hi
__device__ bf16 g_Wfc3[(size_t)EMBED * 3 * EMBED];   // B-split x3 Wfc^T [hi|hi|lo]

// ================= helpers =================
__device__ __forceinline__ uint32_t smem_u32(const void* p) {
    return (uint32_t)__cvta_generic_to_shared((void*)p);
}
#define SWZ128(o) ((o) ^ (((o) >> 3) & 0x70))

__device__ __forceinline__ void cpa16(uint32_t s, const void* g) {
    asm volatile("cp.async.cg.shared.global [%0], [%1], 16;" :: "r"(s), "l"(g));
}
__device__ __forceinline__ void cpa_commit() {
    asm volatile("cp.async.commit_group;" ::: "memory");
}
template <int N> __device__ __forceinline__ void cpa_wait() {
    asm volatile("cp.async.wait_group %0;" :: "n"(N) : "memory");
}
__device__ __forceinline__ void ldsm_x4(uint32_t a, uint32_t& r0, uint32_t& r1,
                                        uint32_t& r2, uint32_t& r3) {
    asm volatile("ldmatrix.sync.aligned.m8n8.x4.shared.b16 {%0,%1,%2,%3}, [%4];"
                 : "=r"(r0), "=r"(r1), "=r"(r2), "=r"(r3) : "r"(a));
}
__device__ __forceinline__ void mma16816(float* c, const uint32_t* a, const uint32_t* b) {
    asm volatile("mma.sync.aligned.m16n8k16.row.col.f32.bf16.bf16.f32 "
                 "{%0,%1,%2,%3}, {%4,%5,%6,%7}, {%8,%9}, {%0,%1,%2,%3};"
                 : "+f"(c[0]), "+f"(c[1]), "+f"(c[2]), "+f"(c[3])
                 : "r"(a[0]), "r"(a[1]), "r"(a[2]), "r"(a[3]), "r"(b[0]), "r"(b[1]));
}
__device__ __forceinline__ void split_pair(float x, float y, bf162& h, bf162& l) {
    h = __floats2bfloat162_rn(x, y);
    l = __floats2bfloat162_rn(x - __bfloat162float(h.x), y - __bfloat162float(h.y));
}
__device__ __forceinline__ float ex2_mufu(float t) {
    float r;
    asm("ex2.approx.f32 %0, %1;" : "=f"(r) : "f"(t));
    return r;
}

// ================= bf16 NT GEMM =================
// D[m,n] = sum_k A[m,k]*B[n,k]; A row-stride lda, B row-stride ldb (bf16, rm).
// MODE 0: fp32 store
// MODE 3: +bias[col]+res[row,col] (fp32) -> A-split x3 bf16 store [hi|lo|hi]
// MODE 4: plain bf16 store
// MODE 5: acc * rowscale[z*sAux + r] -> plain bf16 store
// MODE 6: exp2(acc * escale2) -> plain bf16 store
#define STAGE_B 32768
#define GSMEM   (3 * STAGE_B)   // 98304, 3-stage pipeline; 2 CTAs/SM

template <int MODE>
__global__ void __launch_bounds__(256, 2)
gemm_nt(const bf16* __restrict__ Ag, const bf16* __restrict__ Bg,
        void* __restrict__ Cg, int Kp, int lda, int ldb, int ldc,
        long long sA, long long sB, long long sC,
        const float* __restrict__ aux1, const float* __restrict__ aux2,
        long long sAux, float escale2)
{
    extern __shared__ char smc[];
    const uint32_t sm0 = smem_u32(smc);
    const int tid  = threadIdx.x;
    const int wid  = tid >> 5;
    const int lane = tid & 31;
    const int wm = wid >> 2;        // 0..1
    const int wn = wid & 3;         // 0..3
    const int m0 = blockIdx.y * 128;
    const int n0 = blockIdx.x * 128;

    Ag += (long long)blockIdx.z * sA;
    Bg += (long long)blockIdx.z * sB;

    const bf16* Abase = Ag + (long long)m0 * lda;
    const bf16* Bbase = Bg + (long long)n0 * ldb;

    const int crow = tid >> 3;          // 0..31 base row
    const int ccol = tid & 7;           // 16B chunk

    float acc[4][4][4];
    #pragma unroll
    for (int a = 0; a < 4; a++)
        #pragma unroll
        for (int b = 0; b < 4; b++)
            #pragma unroll
            for (int c = 0; c < 4; c++) acc[a][b][c] = 0.0f;

    const int KT = Kp >> 6;

    auto load_stage = [&](int st, int kt) {
        const uint32_t sa = sm0 + st * STAGE_B;
        const uint32_t sb = sa + 16384;
        const int kofs = kt * 64;
        #pragma unroll
        for (int i = 0; i < 4; i++) {
            const int row = crow + i * 32;
            const uint32_t soff = SWZ128((uint32_t)(row * 128 + ccol * 16));
            cpa16(sa + soff, Abase + (long long)row * lda + kofs + ccol * 8);
            cpa16(sb + soff, Bbase + (long long)row * ldb + kofs + ccol * 8);
        }
    };

    load_stage(0, 0); cpa_commit();
    load_stage(1, 1); cpa_commit();

    int st = 0;                // stage for iteration kt
    for (int kt = 0; kt < KT; ++kt) {
        cpa_wait<1>();
        __syncthreads();

        const uint32_t sa = sm0 + st * STAGE_B;
        const uint32_t sb = sa + 16384;

        #pragma unroll
        for (int ks = 0; ks < 4; ks++) {
            uint32_t afr[4][4];
            uint32_t bfr[4][2];
            const int bcol = ks * 32 + ((lane >> 4) << 4);
            #pragma unroll
            for (int mt = 0; mt < 4; mt++) {
                const int row = wm * 64 + mt * 16 + (lane & 15);
                ldsm_x4(sa + SWZ128((uint32_t)(row * 128 + bcol)),
                        afr[mt][0], afr[mt][1], afr[mt][2], afr[mt][3]);
            }
            #pragma unroll
            for (int np = 0; np < 2; np++) {
                const int row = wn * 32 + np * 16 + (lane & 15);
                uint32_t r0, r1, r2, r3;
                ldsm_x4(sb + SWZ128((uint32_t)(row * 128 + bcol)), r0, r1, r2, r3);
                bfr[2*np][0] = r0;   bfr[2*np][1] = r2;
                bfr[2*np+1][0] = r1; bfr[2*np+1][1] = r3;
            }
            #pragma unroll
            for (int mt = 0; mt < 4; mt++)
                #pragma unroll
                for (int nt = 0; nt < 4; nt++)
                    mma16816(acc[mt][nt], afr[mt], bfr[nt]);
        }

        if (kt + 2 < KT) {
            int nst = st + 2; if (nst >= 3) nst -= 3;
            load_stage(nst, kt + 2);
        }
        cpa_commit();
        if (++st == 3) st = 0;
    }

    // -------- epilogue --------
    const int ld3 = 3 * ldc;
    const float* rs = (MODE == 5) ? (aux1 + (long long)blockIdx.z * sAux) : nullptr;

    #pragma unroll
    for (int mt = 0; mt < 4; mt++) {
        const int r0 = m0 + wm * 64 + mt * 16 + (lane >> 2);
        const int r1 = r0 + 8;
        float rs0 = 1.0f, rs1 = 1.0f;
        if (MODE == 5) { rs0 = rs[r0]; rs1 = rs[r1]; }
        #pragma unroll
        for (int nt = 0; nt < 4; nt++) {
            const int c = n0 + wn * 32 + nt * 8 + (lane & 3) * 2;
            float x0 = acc[mt][nt][0], y0 = acc[mt][nt][1];
            float x1 = acc[mt][nt][2], y1 = acc[mt][nt][3];
            if (MODE == 5) { x0 *= rs0; y0 *= rs0; x1 *= rs1; y1 *= rs1; }
            if (MODE == 6) {
                x0 = ex2_mufu(x0 * escale2); y0 = ex2_mufu(y0 * escale2);
                x1 = ex2_mufu(x1 * escale2); y1 = ex2_mufu(y1 * escale2);
            }
            if (MODE == 3) {
                const float2 bv = *(const float2*)&aux1[c];
                const float2 q0 = *(const float2*)&aux2[(long long)r0 * ldc + c];
                const float2 q1 = *(const float2*)&aux2[(long long)r1 * ldc + c];
                x0 += bv.x + q0.x; y0 += bv.y + q0.y;
                x1 += bv.x + q1.x; y1 += bv.y + q1.y;
                bf16* Cs = (bf16*)Cg;
                bf162 h0, l0, h1, l1;
                split_pair(x0, y0, h0, l0);
                split_pair(x1, y1, h1, l1);
                bf16* p0 = Cs + (long long)r0 * ld3 + c;
                bf16* p1 = Cs + (long long)r1 * ld3 + c;
                *(bf162*)(p0) = h0; *(bf162*)(p0 + ldc) = l0; *(bf162*)(p0 + 2*ldc) = h0;
                *(bf162*)(p1) = h1; *(bf162*)(p1 + ldc) = l1; *(bf162*)(p1 + 2*ldc) = h1;
            } else if (MODE == 0) {
                float* Cf = (float*)Cg + (long long)blockIdx.z * sC;
                *(float2*)&Cf[(long long)r0 * ldc + c] = make_float2(x0, y0);
                *(float2*)&Cf[(long long)r1 * ldc + c] = make_float2(x1, y1);
            } else {
                bf16* Cb = (bf16*)Cg + (long long)blockIdx.z * sC;
                *(bf162*)&Cb[(long long)r0 * ldc + c] = __floats2bfloat162_rn(x0, y0);
                *(bf162*)&Cb[(long long)r1 * ldc + c] = __floats2bfloat162_rn(x1, y1);
            }
        }
    }
}

// ============ fp32 -> bf16 hi convert (elementwise) ============
__global__ void conv_hi(const float* __restrict__ X, bf16* __restrict__ Y)
{
    const long long i4 = (long long)blockIdx.x * blockDim.x + threadIdx.x;
    float4 v = ((const float4*)X)[i4];
    ((bf162*)Y)[i4 * 2]     = __floats2bfloat162_rn(v.x, v.y);
    ((bf162*)Y)[i4 * 2 + 1] = __floats2bfloat162_rn(v.z, v.w);
}

// ============ transpose + bf16 hi: In[R,C] fp32 -> Out[C,R] bf16 ============
// up to 3 tensors selected by blockIdx.z (same shape)
__global__ void w3tr(const float* __restrict__ A0, const float* __restrict__ A1,
                     const float* __restrict__ A2,
                     bf16* __restrict__ B0, bf16* __restrict__ B1,
                     bf16* __restrict__ B2, int R, int C)
{
    const float* In = (blockIdx.z == 0) ? A0 : (blockIdx.z == 1) ? A1 : A2;
    bf16* Out = (blockIdx.z == 0) ? B0 : (blockIdx.z == 1) ? B1 : B2;
    __shared__ float t[32][33];
    const int bx = blockIdx.x * 32;   // C
    const int by = blockIdx.y * 32;   // R
    const int tx = threadIdx.x, ty = threadIdx.y;
    #pragma unroll
    for (int i = ty; i < 32; i += 8)
        t[i][tx] = In[(long long)(by + i) * C + bx + tx];
    __syncthreads();
    #pragma unroll
    for (int i = ty; i < 32; i += 8)
        Out[(long long)(bx + i) * R + by + tx] = __float2bfloat16(t[tx][i]);
}

// ============ B-split x3 + transpose: In[R,C] fp32 -> Out[C,3R] (hi,hi,lo) =======
__global__ void bsplit3_tr(const float* __restrict__ In, bf16* __restrict__ Out,
                           int R, int C)
{
    __shared__ float t[32][33];
    const int bx = blockIdx.x * 32;
    const int by = blockIdx.y * 32;
    const int tx = threadIdx.x, ty = threadIdx.y;
    #pragma unroll
    for (int i = ty; i < 32; i += 8)
        t[i][tx] = In[(long long)(by + i) * C + bx + tx];
    __syncthreads();
    #pragma unroll
    for (int i = ty; i < 32; i += 8) {
        const float v = t[tx][i];
        const bf16 h = __float2bfloat16(v);
        const bf16 l = __float2bfloat16(v - __bfloat162float(h));
        const long long ro = (long long)(bx + i) * (3LL * R) + by + tx;
        Out[ro] = h; Out[ro + R] = h; Out[ro + 2LL * R] = l;
    }
}

// ================= reductions =================
__device__ __forceinline__ float blockReduceSum(float v, float* sh)
{
    const int t = threadIdx.x;
    #pragma unroll
    for (int o = 16; o; o >>= 1) v += __shfl_xor_sync(0xFFFFFFFFu, v, o);
    if ((t & 31) == 0) sh[t >> 5] = v;
    __syncthreads();
    if (t < 32) {
        float r = (t < 8) ? sh[t] : 0.0f;
        #pragma unroll
        for (int o = 4; o; o >>= 1) r += __shfl_xor_sync(0xFFFFFFFFu, r, o);
        if (t == 0) sh[0] = r;
    }
    __syncthreads();
    float r = sh[0];
    __syncthreads();
    return r;
}

// ===== row sums of unnormalized exp-scores -> Zinv =====
__global__ void sumexp_kernel(const bf16* __restrict__ S, float* __restrict__ Zi)
{
    const bf162* p = (const bf162*)(S + (long long)blockIdx.x * SKV);
    const int t = threadIdx.x;
    __shared__ float sh[32];
    float s = 0.0f;
    #pragma unroll
    for (int i = 0; i < 8; i++) {
        float2 v = __bfloat1622float2(p[t + 256 * i]);
        s += v.x + v.y;
    }
    s = blockReduceSum(s, sh);
    if (t == 0) Zi[blockIdx.x] = 1.0f / s;
}

// ================= layernorm =================
__global__ void layernorm_kernel(const float* __restrict__ X,
                                 const float* __restrict__ gamma,
                                 const float* __restrict__ beta,
                                 float* __restrict__ Y)
{
    const float* x = X + (long long)blockIdx.x * EMBED;
    float*       y = Y + (long long)blockIdx.x * EMBED;
    const int t = threadIdx.x;
    __shared__ float sh[32];

    float4 v = *(const float4*)&x[t * 4];
    float s = v.x + v.y + v.z + v.w;
    s = blockReduceSum(s, sh);
    const float mu = s * (1.0f / EMBED);

    float dx = v.x - mu, dy = v.y - mu, dz = v.z - mu, dw = v.w - mu;
    float sq = dx * dx + dy * dy + dz * dz + dw * dw;
    sq = blockReduceSum(sq, sh);
    const float rstd = rsqrtf(sq * (1.0f / EMBED) + 1e-5f);

    float4 g = *(const float4*)&gamma[t * 4];
    float4 b = *(const float4*)&beta[t * 4];
    float4 o;
    o.x = dx * rstd * g.x + b.x;
    o.y = dy * rstd * g.y + b.y;
    o.z = dz * rstd * g.z + b.z;
    o.w = dw * rstd * g.w + b.w;
    *(float4*)&y[t * 4] = o;
}

// ================= launch =================
extern "C" void kernel_launch(void* const* d_in, const int* in_sizes, int n_in,
                              void* d_out, int out_size)
{
    const float* q_feat = (const float*)d_in[0];
    const float* kv     = (const float*)d_in[1];
    const float* Wq     = (const float*)d_in[2];
    const float* Wk     = (const float*)d_in[3];
    const float* Wv     = (const float*)d_in[4];
    const float* Wo     = (const float*)d_in[5];
    const float* bo     = (const float*)d_in[6];
    const float* Wfc    = (const float*)d_in[7];
    const float* gamma  = (const float*)d_in[8];
    const float* beta   = (const float*)d_in[9];
    float* out = (float*)d_out;

    bf16 *qfh, *kvh, *Qh, *Kh, *VT, *S, *Ch, *O1s, *Wq1, *Wk1, *Wv1, *Wo1, *Wfc3;
    float *Zi, *O2;
    cudaGetSymbolAddress((void**)&qfh,  g_qfh);
    cudaGetSymbolAddress((void**)&kvh,  g_kvh);
    cudaGetSymbolAddress((void**)&Qh,   g_Qh);
    cudaGetSymbolAddress((void**)&Kh,   g_Kh);
    cudaGetSymbolAddress((void**)&VT,   g_VT);
    cudaGetSymbolAddress((void**)&S,    g_S);
    cudaGetSymbolAddress((void**)&Zi,   g_Zi);
    cudaGetSymbolAddress((void**)&Ch,   g_Ch);
    cudaGetSymbolAddress((void**)&O1s,  g_O1s);
    cudaGetSymbolAddress((void**)&O2,   g_O2);
    cudaGetSymbolAddress((void**)&Wq1,  g_Wq1);
    cudaGetSymbolAddress((void**)&Wk1,  g_Wk1);
    cudaGetSymbolAddress((void**)&Wv1,  g_Wv1);
    cudaGetSymbolAddress((void**)&Wo1,  g_Wo1);
    cudaGetSymbolAddress((void**)&Wfc3, g_Wfc3);

    cudaFuncSetAttribute(gemm_nt<0>, cudaFuncAttributeMaxDynamicSharedMemorySize, GSMEM);
    cudaFuncSetAttribute(gemm_nt<3>, cudaFuncAttributeMaxDynamicSharedMemorySize, GSMEM);
    cudaFuncSetAttribute(gemm_nt<4>, cudaFuncAttributeMaxDynamicSharedMemorySize, GSMEM);
    cudaFuncSetAttribute(gemm_nt<5>, cudaFuncAttributeMaxDynamicSharedMemorySize, GSMEM);
    cudaFuncSetAttribute(gemm_nt<6>, cudaFuncAttributeMaxDynamicSharedMemorySize, GSMEM);

    const dim3 blk(256);
    const dim3 tblk(32, 8);
    // exp(s/sqrt(512)) = 2^(s * escale2)
    const float escale2 = 0.044194173824159216f * 1.4426950408889634f;

    // launch 0,1: fp32 -> bf16 converts
    conv_hi<<<(MTOK * EMBED / 4) / 256, 256>>>(q_feat, qfh);
    conv_hi<<<(MTOK * EMBED / 4) / 256, 256>>>(kv, kvh);
    // launch 2: fused Wq/Wk/Wv transpose (hi)
    w3tr<<<dim3(HIDDEN/32, EMBED/32, 3), tblk>>>(Wq, Wk, Wv, Wq1, Wk1, Wv1,
                                                 EMBED, HIDDEN);
    // launch 3: Q = qf @ Wq (x1)
    gemm_nt<4><<<dim3(HIDDEN/128, MTOK/128, 1), blk, GSMEM>>>(
        qfh, Wq1, Qh, EMBED, EMBED, EMBED, HIDDEN, 0, 0, 0, nullptr, nullptr, 0, 0.f);
    // launch 4: K = kv @ Wk (x1)
    gemm_nt<4><<<dim3(HIDDEN/128, MTOK/128, 1), blk, GSMEM>>>(
        kvh, Wk1, Kh, EMBED, EMBED, EMBED, HIDDEN, 0, 0, 0, nullptr, nullptr, 0, 0.f);
    // launch 5 (profiled): S = exp2(Q K^T * escale2) per batch
    gemm_nt<6><<<dim3(SKV/128, SQ/128, NB), blk, GSMEM>>>(
        Qh, Kh, S, HIDDEN, HIDDEN, HIDDEN, SKV,
        (long long)SQ * HIDDEN, (long long)SKV * HIDDEN, (long long)SQ * SKV,
        nullptr, nullptr, 0, escale2);
    // launch 6: VT[h,t] = sum_e Wv1[h,e] * kvh[t,e]
    gemm_nt<4><<<dim3(MTOK/128, HIDDEN/128, 1), blk, GSMEM>>>(
        Wv1, kvh, VT, EMBED, EMBED, EMBED, MTOK, 0, 0, 0, nullptr, nullptr, 0, 0.f);
    // launch 7: row sums -> Zinv
    sumexp_kernel<<<MTOK, 256>>>(S, Zi);
    // launch 8: ctx = (S @ V) * Zinv per batch
    gemm_nt<5><<<dim3(HIDDEN/128, SQ/128, NB), blk, GSMEM>>>(
        S, VT, Ch, SKV, SKV, MTOK, HIDDEN,
        (long long)SQ * SKV, (long long)SQ, (long long)SQ * HIDDEN,
        Zi, nullptr, SQ, 0.f);
    // launch 9: Wo^T hi transpose
    w3tr<<<dim3(EMBED/32, HIDDEN/32, 1), tblk>>>(Wo, Wo, Wo, Wo1, Wo1, Wo1,
                                                 HIDDEN, EMBED);
    // launch 10: O1 = ctx @ Wo + bo + q_feat -> A-split x3
    gemm_nt<3><<<dim3(EMBED/128, MTOK/128, 1), blk, GSMEM>>>(
        Ch, Wo1, O1s, HIDDEN, HIDDEN, HIDDEN, EMBED, 0, 0, 0, bo, q_feat, 0, 0.f);
    // launch 11: Wfc B-split x3
    bsplit3_tr<<<dim3(EMBED/32, EMBED/32), tblk>>>(Wfc, Wfc3, EMBED, EMBED);
    // launch 12: O2 = O1 @ Wfc (x3) -> fp32
    gemm_nt<0><<<dim3(EMBED/128, MTOK/128, 1), blk, GSMEM>>>(
        O1s, Wfc3, O2, 3*EMBED, 3*EMBED, 3*EMBED, EMBED, 0, 0, 0, nullptr, nullptr, 0, 0.f);
    // launch 13: layernorm -> out
    layernorm_kernel<<<MTOK, 256>>>(O2, gamma, beta, out);
}